// round 1
// baseline (speedup 1.0000x reference)
#include <cuda_runtime.h>

#define N_NODES 128
#define V_PTS   2048
#define XYZ     63
#define NGROUPS 16   // node groups for partial accumulation
#define NPG     8    // nodes per group (128/16)

// ---- scratch (__device__ globals: allocation-free rule) ----
__device__ float g_ei[N_NODES * 32];
__device__ float g_b1eff[N_NODES * 64];
__device__ float g_e[N_NODES * V_PTS];                 // normalized effective blend weights (0 if masked)
__device__ float g_fpart[NGROUPS * V_PTS * 256];       // per-group partial blended features (33.5 MB)

// ---- output layout (concat of flattened outputs) ----
// c:(1,2048,3)=6144 @0 | d:(1,2048,1)=2048 @6144 | ei:(128,1,32)=4096 @8192
// delta:(128,1,3)=384 @12288 | mean:(128,1,8)=1024 @12672 | logvar:1024 @13696
#define OFF_C      0
#define OFF_D      6144
#define OFF_EI     8192
#define OFF_DELTA  12288
#define OFF_MEAN   12672
#define OFF_LOGVAR 13696

// =====================================================================
// Kernel A: per-node encoder + decoder + effective layer-1 bias
// =====================================================================
__global__ void setup_kernel(
    const float* __restrict__ poses, const float* __restrict__ t_ped,
    const float* __restrict__ w,
    const float* __restrict__ Wec1, const float* __restrict__ bec1,
    const float* __restrict__ Wec21, const float* __restrict__ bec21,
    const float* __restrict__ Wec22, const float* __restrict__ bec22,
    const float* __restrict__ Wdc1, const float* __restrict__ bdc1,
    const float* __restrict__ Wdc21, const float* __restrict__ bdc21,
    const float* __restrict__ Wdc22, const float* __restrict__ bdc22,
    const float* __restrict__ Wf1, const float* __restrict__ bf1,
    float* __restrict__ out)
{
    int n = blockIdx.x;
    int t = threadIdx.x;            // 128 threads
    __shared__ float s_in[88];      // [poses_w(72), t_ped(16)]
    __shared__ float s_net[64];
    __shared__ float s_mean[8];
    __shared__ float s_din[80];
    __shared__ float s_net2[64];
    __shared__ float s_ei[32];

    if (t < 72)       s_in[t] = w[n * 24 + t / 3] * poses[n * 72 + t];
    else if (t < 88)  s_in[t] = t_ped[t - 72];
    __syncthreads();

    if (t < 64) {
        float a = bec1[n * 64 + t];
        const float* Wr = &Wec1[(n * 64 + t) * 88];
        #pragma unroll 8
        for (int c = 0; c < 88; c++) a += Wr[c] * s_in[c];
        s_net[t] = fmaxf(a, 0.f);
    }
    __syncthreads();

    if (t < 8) {
        float m  = bec21[n * 8 + t];
        float lv = bec22[n * 8 + t];
        const float* Wm = &Wec21[(n * 8 + t) * 64];
        const float* Wl = &Wec22[(n * 8 + t) * 64];
        #pragma unroll 8
        for (int c = 0; c < 64; c++) { m += Wm[c] * s_net[c]; lv += Wl[c] * s_net[c]; }
        s_mean[t] = m;
        out[OFF_MEAN   + n * 8 + t] = m;
        out[OFF_LOGVAR + n * 8 + t] = lv;
    }
    __syncthreads();

    if (t < 72)       s_din[t] = s_in[t];
    else if (t < 80)  s_din[t] = s_mean[t - 72];
    __syncthreads();

    if (t < 64) {
        float a = bdc1[n * 64 + t];
        const float* Wr = &Wdc1[(n * 64 + t) * 80];
        #pragma unroll 8
        for (int c = 0; c < 80; c++) a += Wr[c] * s_din[c];
        s_net2[t] = fmaxf(a, 0.f);
    }
    __syncthreads();

    if (t < 32) {
        float a = bdc21[n * 32 + t];
        const float* Wr = &Wdc21[(n * 32 + t) * 64];
        #pragma unroll 8
        for (int c = 0; c < 64; c++) a += Wr[c] * s_net2[c];
        s_ei[t] = a;
        g_ei[n * 32 + t] = a;
        out[OFF_EI + n * 32 + t] = a;
    }
    if (t >= 32 && t < 35) {
        int j = t - 32;
        float a = bdc22[n * 3 + j];
        const float* Wr = &Wdc22[(n * 3 + j) * 64];
        #pragma unroll 8
        for (int c = 0; c < 64; c++) a += Wr[c] * s_net2[c];
        out[OFF_DELTA + n * 3 + j] = a;
    }
    __syncthreads();

    // effective layer-1 bias: bf1 + Wf1[:, :32] @ ei  (ei channels are constant over points)
    if (t < 64) {
        float a = bf1[n * 64 + t];
        const float* Wr = &Wf1[(size_t)(n * 64 + t) * 95];
        #pragma unroll 8
        for (int c = 0; c < 32; c++) a += Wr[c] * s_ei[c];
        g_b1eff[n * 64 + t] = a;
    }
}

// =====================================================================
// Kernel B: RBF blend weights, normalized. Masked -> 0 effective weight.
// denom includes +1e-7 for EVERY node (matches reference exactly).
// =====================================================================
__global__ void bweight_kernel(const float* __restrict__ wpts,
                               const float* __restrict__ nodes_posed)
{
    int v = blockIdx.x * blockDim.x + threadIdx.x;
    if (v >= V_PTS) return;
    float px = wpts[v * 3 + 0], py = wpts[v * 3 + 1], pz = wpts[v * 3 + 2];
    float denom = 0.f;
    for (int n = 0; n < N_NODES; n++) {
        float dx = px - nodes_posed[n * 3 + 0];
        float dy = py - nodes_posed[n * 3 + 1];
        float dz = pz - nodes_posed[n * 3 + 2];
        float d2 = dx * dx + dy * dy + dz * dz;
        float influ = expf(-d2 * (1.0f / 0.18f)) - 0.01f;   // 2*sigma^2 = 0.18
        float e = (influ >= 0.f) ? (influ + 1e-7f) : 0.f;   // masked -> 0 numerator
        denom += fmaxf(influ, 0.f) + 1e-7f;
        g_e[n * V_PTS + v] = e;
    }
    float inv = 1.0f / denom;
    for (int n = 0; n < N_NODES; n++) g_e[n * V_PTS + v] *= inv;
}

// =====================================================================
// Kernel C: feature field (the 15 GFLOP part)
// grid = (16 v-tiles of 128 pts) x (16 node-groups of 8 nodes), 512 thr
// smem float offsets:
// =====================================================================
#define SM_BUFA 0        // 64 x 132 activation buffer ([k][v], transposed)
#define SM_BUFB 8448     // 64 x 132
#define SM_W1   16896    // [k<63][j<64] stride 72
#define SM_W2   21504
#define SM_W3   26112
#define SM_W4   30720    // [k<64][c<256] stride 260
#define SM_B1   47360
#define SM_B2   47424
#define SM_B3   47488
#define SM_B4   47552
#define SM_E    47808
#define SM_TOT  47936    // floats -> 191744 bytes

template <int K>
__device__ __forceinline__ void gemm_layer(const float* __restrict__ in_s,
                                           const float* __restrict__ W_s,
                                           const float* __restrict__ b_s,
                                           float* __restrict__ out_s,
                                           int jq, int vq)
{
    // out[v][j] = relu(b[j] + sum_k W[j][k] * in[v][k]); 4x4 micro-tile
    float a[4][4];
    #pragma unroll
    for (int i = 0; i < 4; i++)
        #pragma unroll
        for (int j = 0; j < 4; j++) a[i][j] = 0.f;

    int v0t = vq * 4, j0t = jq * 4;
    #pragma unroll 3
    for (int k = 0; k < K; k++) {
        float4 av = *(const float4*)&in_s[k * 132 + v0t];
        float4 wj = *(const float4*)&W_s[k * 72 + j0t];
        float avv[4] = {av.x, av.y, av.z, av.w};
        float wjv[4] = {wj.x, wj.y, wj.z, wj.w};
        #pragma unroll
        for (int dv = 0; dv < 4; dv++)
            #pragma unroll
            for (int dj = 0; dj < 4; dj++)
                a[dv][dj] += avv[dv] * wjv[dj];
    }
    #pragma unroll
    for (int dj = 0; dj < 4; dj++) {
        float bj = b_s[j0t + dj];
        float4 o;
        o.x = fmaxf(a[0][dj] + bj, 0.f);
        o.y = fmaxf(a[1][dj] + bj, 0.f);
        o.z = fmaxf(a[2][dj] + bj, 0.f);
        o.w = fmaxf(a[3][dj] + bj, 0.f);
        *(float4*)&out_s[(j0t + dj) * 132 + v0t] = o;  // store transposed for next layer
    }
}

__global__ void __launch_bounds__(512, 1) field_kernel(
    const float* __restrict__ local_coords,
    const float* __restrict__ Wf1,
    const float* __restrict__ Wf2, const float* __restrict__ bf2,
    const float* __restrict__ Wf3, const float* __restrict__ bf3,
    const float* __restrict__ Wf4, const float* __restrict__ bf4)
{
    extern __shared__ float sm[];
    int tid = threadIdx.x;
    int v0 = blockIdx.x * 128;
    int g  = blockIdx.y;

    // persistent per-thread blend accumulator: 8v x 8c of the 128x256 tile
    float acc[8][8];
    #pragma unroll
    for (int i = 0; i < 8; i++)
        #pragma unroll
        for (int j = 0; j < 8; j++) acc[i][j] = 0.f;

    int jq  = tid & 15, vq4 = tid >> 4;   // layers 1-3 mapping (4x4)
    int cq  = tid & 31, vq8 = tid >> 5;   // layer 4 mapping (8v x 4c per half)
    int vv8 = vq8 * 8;

    for (int ni = 0; ni < NPG; ni++) {
        int n = g * NPG + ni;

        // ---- stage node data into smem ----
        for (int idx = tid; idx < 128 * XYZ; idx += 512) {
            int v = idx / XYZ, k = idx - v * XYZ;
            sm[SM_BUFA + k * 132 + v] =
                local_coords[((size_t)n * V_PTS + v0 + v) * XYZ + k];
        }
        for (int idx = tid; idx < 64 * XYZ; idx += 512) {
            int j = idx / XYZ, k = idx - j * XYZ;
            sm[SM_W1 + k * 72 + j] = Wf1[(size_t)(n * 64 + j) * 95 + 32 + k];
        }
        for (int idx = tid; idx < 4096; idx += 512) {
            int j = idx >> 6, k = idx & 63;
            sm[SM_W2 + k * 72 + j] = Wf2[(size_t)n * 4096 + idx];
            sm[SM_W3 + k * 72 + j] = Wf3[(size_t)n * 4096 + idx];
        }
        for (int idx = tid; idx < 16384; idx += 512) {
            int c = idx >> 6, k = idx & 63;
            sm[SM_W4 + k * 260 + c] = Wf4[(size_t)n * 16384 + idx];
        }
        if (tid < 64) {
            sm[SM_B1 + tid] = g_b1eff[n * 64 + tid];
            sm[SM_B2 + tid] = bf2[n * 64 + tid];
            sm[SM_B3 + tid] = bf3[n * 64 + tid];
        }
        if (tid < 256) sm[SM_B4 + tid] = bf4[n * 256 + tid];
        if (tid < 128) sm[SM_E + tid] = g_e[n * V_PTS + v0 + tid];
        __syncthreads();

        // ---- L1: lc(bufA) -> h1(bufB), L2: -> bufA, L3: -> bufB ----
        gemm_layer<63>(sm + SM_BUFA, sm + SM_W1, sm + SM_B1, sm + SM_BUFB, jq, vq4);
        __syncthreads();
        gemm_layer<64>(sm + SM_BUFB, sm + SM_W2, sm + SM_B2, sm + SM_BUFA, jq, vq4);
        __syncthreads();
        gemm_layer<64>(sm + SM_BUFA, sm + SM_W3, sm + SM_B3, sm + SM_BUFB, jq, vq4);
        __syncthreads();

        // ---- L4 (256 outputs) fused with weighted blend-accumulate ----
        #pragma unroll
        for (int h = 0; h < 2; h++) {
            int c0 = h * 128 + cq * 4;
            float tmp[8][4];
            #pragma unroll
            for (int i = 0; i < 8; i++)
                #pragma unroll
                for (int j = 0; j < 4; j++) tmp[i][j] = 0.f;

            #pragma unroll 2
            for (int k = 0; k < 64; k++) {
                float4 a0 = *(const float4*)&sm[SM_BUFB + k * 132 + vv8];
                float4 a1 = *(const float4*)&sm[SM_BUFB + k * 132 + vv8 + 4];
                float4 b  = *(const float4*)&sm[SM_W4 + k * 260 + c0];
                float av[8] = {a0.x, a0.y, a0.z, a0.w, a1.x, a1.y, a1.z, a1.w};
                float bv[4] = {b.x, b.y, b.z, b.w};
                #pragma unroll
                for (int dv = 0; dv < 8; dv++)
                    #pragma unroll
                    for (int dc = 0; dc < 4; dc++)
                        tmp[dv][dc] += av[dv] * bv[dc];
            }
            float4 bb = *(const float4*)&sm[SM_B4 + c0];
            float bbv[4] = {bb.x, bb.y, bb.z, bb.w};
            #pragma unroll
            for (int dv = 0; dv < 8; dv++) {
                float ev = sm[SM_E + vv8 + dv];
                #pragma unroll
                for (int dc = 0; dc < 4; dc++) {
                    float f = fmaxf(tmp[dv][dc] + bbv[dc], 0.f);
                    acc[dv][h * 4 + dc] += ev * f;
                }
            }
        }
        __syncthreads();   // before next node overwrites buffers/weights
    }

    // ---- write this group's partial tile (one write, no atomics) ----
    #pragma unroll
    for (int dv = 0; dv < 8; dv++) {
        size_t base = ((size_t)g * V_PTS + v0 + vv8 + dv) * 256;
        float4 lo = make_float4(acc[dv][0], acc[dv][1], acc[dv][2], acc[dv][3]);
        float4 hi = make_float4(acc[dv][4], acc[dv][5], acc[dv][6], acc[dv][7]);
        *(float4*)&g_fpart[base + cq * 4]       = lo;
        *(float4*)&g_fpart[base + 128 + cq * 4] = hi;
    }
}

// =====================================================================
// Kernel D: reduce partials + NeRF head
// =====================================================================
__global__ void head_kernel(const float* __restrict__ Wc1, const float* __restrict__ bc1,
                            const float* __restrict__ Wc2, const float* __restrict__ bc2,
                            const float* __restrict__ Wd1, const float* __restrict__ bd1,
                            float* __restrict__ out)
{
    int v = blockIdx.x;
    int t = threadIdx.x;   // 64 threads
    __shared__ float f_s[256];
    __shared__ float netc_s[64];

    for (int c = t; c < 256; c += 64) {
        float s = 0.f;
        #pragma unroll
        for (int g2 = 0; g2 < NGROUPS; g2++)
            s += g_fpart[((size_t)g2 * V_PTS + v) * 256 + c];
        f_s[c] = s;
    }
    __syncthreads();

    float a = bc1[t];
    #pragma unroll 8
    for (int c = 0; c < 256; c++) a += f_s[c] * Wc1[c * 64 + t];
    netc_s[t] = fmaxf(a, 0.f);
    __syncthreads();

    if (t < 3) {
        float r = bc2[t];
        #pragma unroll 8
        for (int j = 0; j < 64; j++) r += netc_s[j] * Wc2[j * 3 + t];
        out[OFF_C + v * 3 + t] = r;
    } else if (t == 3) {
        float r = bd1[0];
        #pragma unroll 8
        for (int c = 0; c < 256; c++) r += f_s[c] * Wd1[c];
        out[OFF_D + v] = fmaxf(r, 0.f);
    }
}

// =====================================================================
extern "C" void kernel_launch(void* const* d_in, const int* in_sizes, int n_in,
                              void* d_out, int out_size)
{
    const float* poses = (const float*)d_in[0];
    const float* t_ped = (const float*)d_in[1];
    const float* w     = (const float*)d_in[2];
    const float* wpts  = (const float*)d_in[3];
    const float* nodes = (const float*)d_in[4];
    const float* lc    = (const float*)d_in[5];
    const float *Wec1 = (const float*)d_in[6],  *bec1 = (const float*)d_in[7];
    const float *Wec21= (const float*)d_in[8],  *bec21= (const float*)d_in[9];
    const float *Wec22= (const float*)d_in[10], *bec22= (const float*)d_in[11];
    const float *Wdc1 = (const float*)d_in[12], *bdc1 = (const float*)d_in[13];
    const float *Wdc21= (const float*)d_in[14], *bdc21= (const float*)d_in[15];
    const float *Wdc22= (const float*)d_in[16], *bdc22= (const float*)d_in[17];
    const float *Wf1  = (const float*)d_in[18], *bf1  = (const float*)d_in[19];
    const float *Wf2  = (const float*)d_in[20], *bf2  = (const float*)d_in[21];
    const float *Wf3  = (const float*)d_in[22], *bf3  = (const float*)d_in[23];
    const float *Wf4  = (const float*)d_in[24], *bf4  = (const float*)d_in[25];
    const float *Wc1  = (const float*)d_in[26], *bc1  = (const float*)d_in[27];
    const float *Wc2  = (const float*)d_in[28], *bc2  = (const float*)d_in[29];
    const float *Wd1  = (const float*)d_in[30], *bd1  = (const float*)d_in[31];
    float* out = (float*)d_out;

    setup_kernel<<<N_NODES, 128>>>(poses, t_ped, w,
                                   Wec1, bec1, Wec21, bec21, Wec22, bec22,
                                   Wdc1, bdc1, Wdc21, bdc21, Wdc22, bdc22,
                                   Wf1, bf1, out);
    bweight_kernel<<<V_PTS / 256, 256>>>(wpts, nodes);

    cudaFuncSetAttribute(field_kernel,
                         cudaFuncAttributeMaxDynamicSharedMemorySize,
                         SM_TOT * (int)sizeof(float));
    field_kernel<<<dim3(V_PTS / 128, NGROUPS), 512, SM_TOT * sizeof(float)>>>(
        lc, Wf1, Wf2, bf2, Wf3, bf3, Wf4, bf4);

    head_kernel<<<V_PTS, 64>>>(Wc1, bc1, Wc2, bc2, Wd1, bd1, out);
}